// round 1
// baseline (speedup 1.0000x reference)
#include <cuda_runtime.h>
#include <math.h>

#define BD 2
#define VD 65536
#define CIND 128
#define COUTD 256
#define TDIMD 512
#define EPSF 1e-5f

// ---------------- scratch (device globals, no allocation) ----------------
__device__ float g_hn1[(size_t)BD * VD * CIND];    // 16.7M floats
__device__ float g_h  [(size_t)BD * VD * COUTD];   // 33.6M floats
__device__ float g_hn2[(size_t)BD * VD * COUTD];   // 33.6M floats
__device__ float g_sum1[64], g_sumsq1[64], g_mean1[64], g_rstd1[64];
__device__ float g_sum2[64], g_sumsq2[64], g_mean2[64], g_rstd2[64];
__device__ float g_t[BD * COUTD];

__device__ __forceinline__ float silu_f(float z) {
    return z / (1.f + __expf(-z));
}

// ---------------- kernel 0: zero the stat accumulators ----------------
__global__ void zero_stats_kernel() {
    int i = threadIdx.x;
    if (i < 64) {
        g_sum1[i] = 0.f; g_sumsq1[i] = 0.f;
        g_sum2[i] = 0.f; g_sumsq2[i] = 0.f;
    }
}

// ---------------- kernel 1: GN1 partial stats ----------------
// grid = 1024 blocks, each handles 128 consecutive rows (all same batch).
// group size = CIN/32 = 4 channels = one float4.
__global__ __launch_bounds__(256) void gn1_stats_kernel(const float* __restrict__ x) {
    int rowStart = blockIdx.x * 128;
    int b = rowStart >> 16;
    int tid = threadIdx.x;
    int g = tid & 31;
    int sub = tid >> 5;

    float s = 0.f, ss = 0.f;
    for (int r = sub; r < 128; r += 8) {
        float4 v = *reinterpret_cast<const float4*>(&x[(size_t)(rowStart + r) * CIND + g * 4]);
        s  += v.x + v.y + v.z + v.w;
        ss += v.x * v.x + v.y * v.y + v.z * v.z + v.w * v.w;
    }
    __shared__ float sh[32], shs[32];
    if (tid < 32) { sh[tid] = 0.f; shs[tid] = 0.f; }
    __syncthreads();
    atomicAdd(&sh[g], s);
    atomicAdd(&shs[g], ss);
    __syncthreads();
    if (tid < 32) {
        atomicAdd(&g_sum1[b * 32 + tid], sh[tid]);
        atomicAdd(&g_sumsq1[b * 32 + tid], shs[tid]);
    }
}

__global__ void finalize1_kernel() {
    int i = threadIdx.x;
    if (i < 64) {
        const float inv = 1.f / (float)(VD * 4);
        float m = g_sum1[i] * inv;
        float var = g_sumsq1[i] * inv - m * m;
        g_mean1[i] = m;
        g_rstd1[i] = rsqrtf(var + EPSF);
    }
}

__global__ void finalize2_kernel() {
    int i = threadIdx.x;
    if (i < 64) {
        const float inv = 1.f / (float)(VD * 8);
        float m = g_sum2[i] * inv;
        float var = g_sumsq2[i] * inv - m * m;
        g_mean2[i] = m;
        g_rstd2[i] = rsqrtf(var + EPSF);
    }
}

// ---------------- t vector: t[b,o] = silu(t_emb[b]) . wt[o] + bt[o] ----------------
__global__ __launch_bounds__(256) void t_kernel(const float* __restrict__ t_emb,
                                                const float* __restrict__ wt,
                                                const float* __restrict__ bt) {
    __shared__ float te[TDIMD];
    int b = blockIdx.x;
    int tid = threadIdx.x;
    for (int i = tid; i < TDIMD; i += 256) {
        te[i] = silu_f(t_emb[b * TDIMD + i]);
    }
    __syncthreads();
    float acc = bt[tid];
    const float* wrow = &wt[(size_t)tid * TDIMD];
    #pragma unroll 4
    for (int k = 0; k < TDIMD; k += 4) {
        float4 w4 = *reinterpret_cast<const float4*>(&wrow[k]);
        acc += te[k] * w4.x + te[k + 1] * w4.y + te[k + 2] * w4.z + te[k + 3] * w4.w;
    }
    g_t[b * COUTD + tid] = acc;
}

// ---------------- hn1 = silu(gn1(x)) ----------------
// float4 per thread; group = float4 index within row (group size 4).
__global__ __launch_bounds__(256) void hn1_kernel(const float* __restrict__ x,
                                                  const float* __restrict__ w,
                                                  const float* __restrict__ bb) {
    int idx = blockIdx.x * 256 + threadIdx.x;        // < B*V*CIN/4 = 4194304
    int g = idx & 31;
    int row = idx >> 5;
    int b = row >> 16;
    float m = g_mean1[b * 32 + g];
    float rs = g_rstd1[b * 32 + g];
    float4 xv = *reinterpret_cast<const float4*>(&x[(size_t)idx * 4]);
    int c0 = g * 4;
    float4 wv = *reinterpret_cast<const float4*>(&w[c0]);
    float4 bv = *reinterpret_cast<const float4*>(&bb[c0]);
    float4 o;
    o.x = silu_f((xv.x - m) * rs * wv.x + bv.x);
    o.y = silu_f((xv.y - m) * rs * wv.y + bv.y);
    o.z = silu_f((xv.z - m) * rs * wv.z + bv.z);
    o.w = silu_f((xv.w - m) * rs * wv.w + bv.w);
    *reinterpret_cast<float4*>(&g_hn1[(size_t)idx * 4]) = o;
}

// ---------------- hn2 = silu(gn2(h)) ----------------
// COUT=256, group size 8 → group = (float4_in_row) >> 1.
__global__ __launch_bounds__(256) void hn2_kernel(const float* __restrict__ w,
                                                  const float* __restrict__ bb) {
    int idx = blockIdx.x * 256 + threadIdx.x;        // < B*V*COUT/4 = 8388608
    int c4 = idx & 63;
    int g = c4 >> 1;
    int row = idx >> 6;
    int b = row >> 16;
    float m = g_mean2[b * 32 + g];
    float rs = g_rstd2[b * 32 + g];
    float4 xv = *reinterpret_cast<const float4*>(&g_h[(size_t)idx * 4]);
    int c0 = c4 * 4;
    float4 wv = *reinterpret_cast<const float4*>(&w[c0]);
    float4 bv = *reinterpret_cast<const float4*>(&bb[c0]);
    float4 o;
    o.x = silu_f((xv.x - m) * rs * wv.x + bv.x);
    o.y = silu_f((xv.y - m) * rs * wv.y + bv.y);
    o.z = silu_f((xv.z - m) * rs * wv.z + bv.z);
    o.w = silu_f((xv.w - m) * rs * wv.w + bv.w);
    *reinterpret_cast<float4*>(&g_hn2[(size_t)idx * 4]) = o;
}

// ---------------- conv1: h = gatherGEMM(hn1, W1) + b1 + t ; fused GN2 stats ----------------
// tile 64x64, BK=32, 256 threads, 4x4 micro-tile.
__global__ __launch_bounds__(256) void conv1_kernel(const float* __restrict__ W1,
                                                    const float* __restrict__ b1,
                                                    const int* __restrict__ neigh) {
    __shared__ float As[32][68];
    __shared__ float Bs[32][68];
    __shared__ int nidx[9][64];
    __shared__ float gsum[8], gss[8];

    int tid = threadIdx.x;
    int rowStart = blockIdx.x * 64;
    int b = rowStart >> 16;
    int v0 = rowStart & (VD - 1);
    int col0 = blockIdx.y * 64;

    for (int i = tid; i < 576; i += 256) {
        int n = i / 64, r = i - n * 64;
        nidx[n][r] = neigh[(v0 + r) * 9 + n];
    }
    if (tid < 8) { gsum[tid] = 0.f; gss[tid] = 0.f; }
    __syncthreads();

    int tx = tid & 15, ty = tid >> 4;
    float acc[4][4] = {};

    for (int chunk = 0; chunk < 36; ++chunk) {
        int n = chunk >> 2;
        int cc = (chunk & 3) << 5;
        #pragma unroll
        for (int i = 0; i < 2; ++i) {
            int idx = tid + i * 256;
            int r = idx >> 3, k4 = idx & 7;
            int src = nidx[n][r];
            float4 av = *reinterpret_cast<const float4*>(
                &g_hn1[((size_t)((b << 16) + src)) * CIND + cc + (k4 << 2)]);
            As[k4 * 4 + 0][r] = av.x; As[k4 * 4 + 1][r] = av.y;
            As[k4 * 4 + 2][r] = av.z; As[k4 * 4 + 3][r] = av.w;
            float4 wv = *reinterpret_cast<const float4*>(
                &W1[(size_t)(col0 + r) * 1152 + n * CIND + cc + (k4 << 2)]);
            Bs[k4 * 4 + 0][r] = wv.x; Bs[k4 * 4 + 1][r] = wv.y;
            Bs[k4 * 4 + 2][r] = wv.z; Bs[k4 * 4 + 3][r] = wv.w;
        }
        __syncthreads();
        #pragma unroll
        for (int kk = 0; kk < 32; ++kk) {
            float4 a = *reinterpret_cast<const float4*>(&As[kk][ty << 2]);
            float4 w = *reinterpret_cast<const float4*>(&Bs[kk][tx << 2]);
            acc[0][0] += a.x * w.x; acc[0][1] += a.x * w.y; acc[0][2] += a.x * w.z; acc[0][3] += a.x * w.w;
            acc[1][0] += a.y * w.x; acc[1][1] += a.y * w.y; acc[1][2] += a.y * w.z; acc[1][3] += a.y * w.w;
            acc[2][0] += a.z * w.x; acc[2][1] += a.z * w.y; acc[2][2] += a.z * w.z; acc[2][3] += a.z * w.w;
            acc[3][0] += a.w * w.x; acc[3][1] += a.w * w.y; acc[3][2] += a.w * w.z; acc[3][3] += a.w * w.w;
        }
        __syncthreads();
    }

    // epilogue: + b1 + t, store h, accumulate GN2 partial stats
    int cbase = col0 + (tx << 2);
    float4 bias = *reinterpret_cast<const float4*>(&b1[cbase]);
    float4 tv = *reinterpret_cast<const float4*>(&g_t[b * COUTD + cbase]);
    bias.x += tv.x; bias.y += tv.y; bias.z += tv.z; bias.w += tv.w;

    float lsum = 0.f, lss = 0.f;
    #pragma unroll
    for (int i = 0; i < 4; ++i) {
        int row = rowStart + (ty << 2) + i;
        float4 o;
        o.x = acc[i][0] + bias.x;
        o.y = acc[i][1] + bias.y;
        o.z = acc[i][2] + bias.z;
        o.w = acc[i][3] + bias.w;
        *reinterpret_cast<float4*>(&g_h[(size_t)row * COUTD + cbase]) = o;
        lsum += o.x + o.y + o.z + o.w;
        lss  += o.x * o.x + o.y * o.y + o.z * o.z + o.w * o.w;
    }
    atomicAdd(&gsum[tx >> 1], lsum);
    atomicAdd(&gss[tx >> 1], lss);
    __syncthreads();
    if (tid < 8) {
        int gidx = b * 32 + (col0 >> 3) + tid;
        atomicAdd(&g_sum2[gidx], gsum[tid]);
        atomicAdd(&g_sumsq2[gidx], gss[tid]);
    }
}

// ---------------- conv2: out = gatherGEMM(hn2, W2) + x@ws^T + b2 + bs ----------------
__global__ __launch_bounds__(256) void conv2_kernel(const float* __restrict__ x,
                                                    const float* __restrict__ W2,
                                                    const float* __restrict__ b2,
                                                    const float* __restrict__ ws,
                                                    const float* __restrict__ bs,
                                                    const int* __restrict__ neigh,
                                                    float* __restrict__ out) {
    __shared__ float As[32][68];
    __shared__ float Bs[32][68];
    __shared__ int nidx[9][64];

    int tid = threadIdx.x;
    int rowStart = blockIdx.x * 64;
    int b = rowStart >> 16;
    int v0 = rowStart & (VD - 1);
    int col0 = blockIdx.y * 64;

    for (int i = tid; i < 576; i += 256) {
        int n = i / 64, r = i - n * 64;
        nidx[n][r] = neigh[(v0 + r) * 9 + n];
    }
    __syncthreads();

    int tx = tid & 15, ty = tid >> 4;
    float acc[4][4] = {};

    // 72 chunks of gathered hn2 (9 neighbors x 8 chunks of 32), then 4 chunks of x (shortcut)
    for (int chunk = 0; chunk < 76; ++chunk) {
        #pragma unroll
        for (int i = 0; i < 2; ++i) {
            int idx = tid + i * 256;
            int r = idx >> 3, k4 = idx & 7;
            float4 av, wv;
            if (chunk < 72) {
                int n = chunk >> 3;
                int cc = (chunk & 7) << 5;
                int src = nidx[n][r];
                av = *reinterpret_cast<const float4*>(
                    &g_hn2[((size_t)((b << 16) + src)) * COUTD + cc + (k4 << 2)]);
                wv = *reinterpret_cast<const float4*>(
                    &W2[(size_t)(col0 + r) * 2304 + n * COUTD + cc + (k4 << 2)]);
            } else {
                int cc = (chunk - 72) << 5;
                av = *reinterpret_cast<const float4*>(
                    &x[(size_t)(rowStart + r) * CIND + cc + (k4 << 2)]);
                wv = *reinterpret_cast<const float4*>(
                    &ws[(size_t)(col0 + r) * CIND + cc + (k4 << 2)]);
            }
            As[k4 * 4 + 0][r] = av.x; As[k4 * 4 + 1][r] = av.y;
            As[k4 * 4 + 2][r] = av.z; As[k4 * 4 + 3][r] = av.w;
            Bs[k4 * 4 + 0][r] = wv.x; Bs[k4 * 4 + 1][r] = wv.y;
            Bs[k4 * 4 + 2][r] = wv.z; Bs[k4 * 4 + 3][r] = wv.w;
        }
        __syncthreads();
        #pragma unroll
        for (int kk = 0; kk < 32; ++kk) {
            float4 a = *reinterpret_cast<const float4*>(&As[kk][ty << 2]);
            float4 w = *reinterpret_cast<const float4*>(&Bs[kk][tx << 2]);
            acc[0][0] += a.x * w.x; acc[0][1] += a.x * w.y; acc[0][2] += a.x * w.z; acc[0][3] += a.x * w.w;
            acc[1][0] += a.y * w.x; acc[1][1] += a.y * w.y; acc[1][2] += a.y * w.z; acc[1][3] += a.y * w.w;
            acc[2][0] += a.z * w.x; acc[2][1] += a.z * w.y; acc[2][2] += a.z * w.z; acc[2][3] += a.z * w.w;
            acc[3][0] += a.w * w.x; acc[3][1] += a.w * w.y; acc[3][2] += a.w * w.z; acc[3][3] += a.w * w.w;
        }
        __syncthreads();
    }

    int cbase = col0 + (tx << 2);
    float4 bias = *reinterpret_cast<const float4*>(&b2[cbase]);
    float4 bsv = *reinterpret_cast<const float4*>(&bs[cbase]);
    bias.x += bsv.x; bias.y += bsv.y; bias.z += bsv.z; bias.w += bsv.w;

    #pragma unroll
    for (int i = 0; i < 4; ++i) {
        int row = rowStart + (ty << 2) + i;
        float4 o;
        o.x = acc[i][0] + bias.x;
        o.y = acc[i][1] + bias.y;
        o.z = acc[i][2] + bias.z;
        o.w = acc[i][3] + bias.w;
        *reinterpret_cast<float4*>(&out[(size_t)row * COUTD + cbase]) = o;
    }
}

// ---------------- launch ----------------
extern "C" void kernel_launch(void* const* d_in, const int* in_sizes, int n_in,
                              void* d_out, int out_size) {
    const float* x      = (const float*)d_in[0];
    const float* t_emb  = (const float*)d_in[1];
    const int*   neigh  = (const int*)d_in[2];
    const float* gn1_w  = (const float*)d_in[3];
    const float* gn1_b  = (const float*)d_in[4];
    const float* w1     = (const float*)d_in[5];
    const float* b1     = (const float*)d_in[6];
    const float* wt     = (const float*)d_in[7];
    const float* bt     = (const float*)d_in[8];
    const float* gn2_w  = (const float*)d_in[9];
    const float* gn2_b  = (const float*)d_in[10];
    const float* w2     = (const float*)d_in[11];
    const float* b2     = (const float*)d_in[12];
    const float* ws     = (const float*)d_in[13];
    const float* bs     = (const float*)d_in[14];
    float* out = (float*)d_out;

    zero_stats_kernel<<<1, 256>>>();
    gn1_stats_kernel<<<1024, 256>>>(x);
    finalize1_kernel<<<1, 64>>>();
    t_kernel<<<2, 256>>>(t_emb, wt, bt);
    hn1_kernel<<<16384, 256>>>(x, gn1_w, gn1_b);
    conv1_kernel<<<dim3(2048, 4), 256>>>(w1, b1, neigh);
    finalize2_kernel<<<1, 64>>>();
    hn2_kernel<<<32768, 256>>>(gn2_w, gn2_b);
    conv2_kernel<<<dim3(2048, 4), 256>>>(x, w2, b2, ws, bs, neigh, out);
}

// round 4
// speedup vs baseline: 2.7766x; 2.7766x over previous
#include <cuda_runtime.h>
#include <cuda_bf16.h>
#include <cstdint>
#include <math.h>

#define BD 2
#define VD 65536
#define CIND 128
#define COUTD 256
#define TDIMD 512
#define EPSF 1e-5f

// ================= scratch (device globals) =================
__device__ __nv_bfloat16 g_hn1h[(size_t)BD * VD * CIND];
__device__ __nv_bfloat16 g_hn1l[(size_t)BD * VD * CIND];
__device__ __nv_bfloat16 g_hn2h[(size_t)BD * VD * COUTD];
__device__ __nv_bfloat16 g_hn2l[(size_t)BD * VD * COUTD];
__device__ __nv_bfloat16 g_xh[(size_t)BD * VD * CIND];
__device__ __nv_bfloat16 g_xl[(size_t)BD * VD * CIND];
__device__ float g_h[(size_t)BD * VD * COUTD];
__device__ __nv_bfloat16 g_w1h[COUTD * 9 * CIND],  g_w1l[COUTD * 9 * CIND];
__device__ __nv_bfloat16 g_w2h[COUTD * 9 * COUTD], g_w2l[COUTD * 9 * COUTD];
__device__ __nv_bfloat16 g_wsh[COUTD * CIND],      g_wsl[COUTD * CIND];
__device__ float g_sum1[64], g_sumsq1[64], g_mean1[64], g_rstd1[64];
__device__ float g_sum2[64], g_sumsq2[64], g_mean2[64], g_rstd2[64];
__device__ float g_t[BD * COUTD];

__device__ __forceinline__ float silu_f(float z) { return z / (1.f + __expf(-z)); }
__device__ __forceinline__ void split1(float v, __nv_bfloat16& h, __nv_bfloat16& l) {
    h = __float2bfloat16_rn(v);
    l = __float2bfloat16_rn(v - __bfloat162float(h));
}
__device__ __forceinline__ uint32_t smem_to_u32(const void* p) {
    uint32_t a;
    asm("{ .reg .u64 t; cvta.to.shared.u64 t, %1; cvt.u32.u64 %0, t; }" : "=r"(a) : "l"(p));
    return a;
}

#define LDSM4(r0, r1, r2, r3, addr) \
    asm volatile("ldmatrix.sync.aligned.m8n8.x4.shared.b16 {%0,%1,%2,%3}, [%4];" \
        : "=r"(r0), "=r"(r1), "=r"(r2), "=r"(r3) : "r"(addr))

#define MMA_BF16(d, a, b) \
    asm volatile("mma.sync.aligned.m16n8k16.row.col.f32.bf16.bf16.f32 " \
        "{%0,%1,%2,%3},{%4,%5,%6,%7},{%8,%9},{%0,%1,%2,%3};" \
        : "+f"((d)[0]), "+f"((d)[1]), "+f"((d)[2]), "+f"((d)[3]) \
        : "r"((a)[0]), "r"((a)[1]), "r"((a)[2]), "r"((a)[3]), "r"((b)[0]), "r"((b)[1]))

// ================= small kernels =================
__global__ void zero_stats_kernel() {
    int i = threadIdx.x;
    if (i < 64) { g_sum1[i] = 0.f; g_sumsq1[i] = 0.f; g_sum2[i] = 0.f; g_sumsq2[i] = 0.f; }
}

__global__ __launch_bounds__(256) void gn1_stats_kernel(const float* __restrict__ x) {
    int rowStart = blockIdx.x * 128;
    int b = rowStart >> 16;
    int tid = threadIdx.x;
    int g = tid & 31, sub = tid >> 5;
    float s = 0.f, ss = 0.f;
    for (int r = sub; r < 128; r += 8) {
        float4 v = *reinterpret_cast<const float4*>(&x[(size_t)(rowStart + r) * CIND + g * 4]);
        s  += v.x + v.y + v.z + v.w;
        ss += v.x * v.x + v.y * v.y + v.z * v.z + v.w * v.w;
    }
    __shared__ float sh[32], shs[32];
    if (tid < 32) { sh[tid] = 0.f; shs[tid] = 0.f; }
    __syncthreads();
    atomicAdd(&sh[g], s); atomicAdd(&shs[g], ss);
    __syncthreads();
    if (tid < 32) { atomicAdd(&g_sum1[b * 32 + tid], sh[tid]); atomicAdd(&g_sumsq1[b * 32 + tid], shs[tid]); }
}

__global__ void finalize1_kernel() {
    int i = threadIdx.x;
    if (i < 64) {
        const float inv = 1.f / (float)(VD * 4);
        float m = g_sum1[i] * inv;
        float var = g_sumsq1[i] * inv - m * m;
        g_mean1[i] = m; g_rstd1[i] = rsqrtf(var + EPSF);
    }
}
__global__ void finalize2_kernel() {
    int i = threadIdx.x;
    if (i < 64) {
        const float inv = 1.f / (float)(VD * 8);
        float m = g_sum2[i] * inv;
        float var = g_sumsq2[i] * inv - m * m;
        g_mean2[i] = m; g_rstd2[i] = rsqrtf(var + EPSF);
    }
}

__global__ __launch_bounds__(256) void t_kernel(const float* __restrict__ t_emb,
                                                const float* __restrict__ wt,
                                                const float* __restrict__ bt) {
    __shared__ float te[TDIMD];
    int b = blockIdx.x, tid = threadIdx.x;
    for (int i = tid; i < TDIMD; i += 256) te[i] = silu_f(t_emb[b * TDIMD + i]);
    __syncthreads();
    float acc = bt[tid];
    const float* wrow = &wt[(size_t)tid * TDIMD];
    #pragma unroll 4
    for (int k = 0; k < TDIMD; k += 4) {
        float4 w4 = *reinterpret_cast<const float4*>(&wrow[k]);
        acc += te[k] * w4.x + te[k+1] * w4.y + te[k+2] * w4.z + te[k+3] * w4.w;
    }
    g_t[b * COUTD + tid] = acc;
}

__global__ __launch_bounds__(256) void prep_w_kernel(const float* __restrict__ w1,
                                                     const float* __restrict__ w2,
                                                     const float* __restrict__ ws) {
    int idx = blockIdx.x * 256 + threadIdx.x;
    const int N1 = COUTD * 9 * CIND;
    const int N2 = COUTD * 9 * COUTD;
    const int NS = COUTD * CIND;
    if (idx < N1)            split1(w1[idx], g_w1h[idx], g_w1l[idx]);
    else if (idx < N1 + N2)  { int j = idx - N1; split1(w2[j], g_w2h[j], g_w2l[j]); }
    else if (idx < N1 + N2 + NS) { int j = idx - N1 - N2; split1(ws[j], g_wsh[j], g_wsl[j]); }
}

__global__ __launch_bounds__(256) void hn1split_kernel(const float* __restrict__ x,
                                                       const float* __restrict__ w,
                                                       const float* __restrict__ bb) {
    int idx = blockIdx.x * 256 + threadIdx.x;
    int g = idx & 31;
    int row = idx >> 5;
    int b = row >> 16;
    float m = g_mean1[b * 32 + g];
    float rs = g_rstd1[b * 32 + g];
    float4 xv = *reinterpret_cast<const float4*>(&x[(size_t)idx * 4]);
    int c0 = g * 4;
    float4 wv = *reinterpret_cast<const float4*>(&w[c0]);
    float4 bv = *reinterpret_cast<const float4*>(&bb[c0]);
    float o0 = silu_f((xv.x - m) * rs * wv.x + bv.x);
    float o1 = silu_f((xv.y - m) * rs * wv.y + bv.y);
    float o2 = silu_f((xv.z - m) * rs * wv.z + bv.z);
    float o3 = silu_f((xv.w - m) * rs * wv.w + bv.w);
    union { __nv_bfloat16 b[4]; uint2 u; } H, L, XH, XL;
    split1(o0, H.b[0], L.b[0]); split1(o1, H.b[1], L.b[1]);
    split1(o2, H.b[2], L.b[2]); split1(o3, H.b[3], L.b[3]);
    split1(xv.x, XH.b[0], XL.b[0]); split1(xv.y, XH.b[1], XL.b[1]);
    split1(xv.z, XH.b[2], XL.b[2]); split1(xv.w, XH.b[3], XL.b[3]);
    *reinterpret_cast<uint2*>(&g_hn1h[(size_t)idx * 4]) = H.u;
    *reinterpret_cast<uint2*>(&g_hn1l[(size_t)idx * 4]) = L.u;
    *reinterpret_cast<uint2*>(&g_xh[(size_t)idx * 4]) = XH.u;
    *reinterpret_cast<uint2*>(&g_xl[(size_t)idx * 4]) = XL.u;
}

__global__ __launch_bounds__(256) void hn2split_kernel(const float* __restrict__ w,
                                                       const float* __restrict__ bb) {
    int idx = blockIdx.x * 256 + threadIdx.x;
    int c4 = idx & 63;
    int g = c4 >> 1;
    int row = idx >> 6;
    int b = row >> 16;
    float m = g_mean2[b * 32 + g];
    float rs = g_rstd2[b * 32 + g];
    float4 xv = *reinterpret_cast<const float4*>(&g_h[(size_t)idx * 4]);
    int c0 = c4 * 4;
    float4 wv = *reinterpret_cast<const float4*>(&w[c0]);
    float4 bv = *reinterpret_cast<const float4*>(&bb[c0]);
    float o0 = silu_f((xv.x - m) * rs * wv.x + bv.x);
    float o1 = silu_f((xv.y - m) * rs * wv.y + bv.y);
    float o2 = silu_f((xv.z - m) * rs * wv.z + bv.z);
    float o3 = silu_f((xv.w - m) * rs * wv.w + bv.w);
    union { __nv_bfloat16 b[4]; uint2 u; } H, L;
    split1(o0, H.b[0], L.b[0]); split1(o1, H.b[1], L.b[1]);
    split1(o2, H.b[2], L.b[2]); split1(o3, H.b[3], L.b[3]);
    *reinterpret_cast<uint2*>(&g_hn2h[(size_t)idx * 4]) = H.u;
    *reinterpret_cast<uint2*>(&g_hn2l[(size_t)idx * 4]) = L.u;
}

// ================= mma.sync gather-GEMM =================
// CTA 128x128 tile, 8 warps (2m x 4n), warp tile 64x32, K-chunk 32, double buffer.
// 3-pass bf16 split: Ah*Bh + Ah*Bl + Al*Bh, fp32 accumulate in registers.
// smem rows: 32 bf16 payload (64B) padded to 80B -> conflict-free ldmatrix.
#define SM_NIDX 0
#define SM_SG   4608
#define SM_SQ   4672
#define SM_BUF  4864
#define BUFSZ   40960
#define OFF_AH  0
#define OFF_AL  10240
#define OFF_BH  20480
#define OFF_BL  30720
#define SMEMSZ  (SM_BUF + 2 * BUFSZ)   // 86784

template<bool CONV2>
__device__ __forceinline__ void gload(int c, int tid, int rowStart, int colB,
                                      size_t bbase, const int* s_nidx,
                                      uint4 sa[4], uint4 sb[4]) {
    const int KW = CONV2 ? 2304 : 1152;
    int r = tid >> 1, h = tid & 1;
    const __nv_bfloat16 *pah, *pal, *pwh, *pwl;
    if (!CONV2) {
        int n = c >> 2, koff = (c & 3) << 5;
        int src = s_nidx[n * 128 + r];
        size_t base = (bbase + (size_t)src) * CIND + koff;
        pah = g_hn1h + base; pal = g_hn1l + base;
        pwh = g_w1h + (size_t)(colB + r) * KW + c * 32;
        pwl = g_w1l + (size_t)(colB + r) * KW + c * 32;
    } else if (c < 72) {
        int n = c >> 3, koff = (c & 7) << 5;
        int src = s_nidx[n * 128 + r];
        size_t base = (bbase + (size_t)src) * COUTD + koff;
        pah = g_hn2h + base; pal = g_hn2l + base;
        pwh = g_w2h + (size_t)(colB + r) * KW + c * 32;
        pwl = g_w2l + (size_t)(colB + r) * KW + c * 32;
    } else {
        int koff = (c - 72) << 5;
        size_t base = (size_t)(rowStart + r) * CIND + koff;
        pah = g_xh + base; pal = g_xl + base;
        pwh = g_wsh + (size_t)(colB + r) * CIND + koff;
        pwl = g_wsl + (size_t)(colB + r) * CIND + koff;
    }
    sa[0] = ((const uint4*)pah)[h * 2]; sa[1] = ((const uint4*)pah)[h * 2 + 1];
    sa[2] = ((const uint4*)pal)[h * 2]; sa[3] = ((const uint4*)pal)[h * 2 + 1];
    sb[0] = ((const uint4*)pwh)[h * 2]; sb[1] = ((const uint4*)pwh)[h * 2 + 1];
    sb[2] = ((const uint4*)pwl)[h * 2]; sb[3] = ((const uint4*)pwl)[h * 2 + 1];
}

__device__ __forceinline__ void sstore(char* bufp, int tid,
                                       const uint4 sa[4], const uint4 sb[4]) {
    int r = tid >> 1, h = tid & 1;
    int off = r * 80 + h * 32;
    *(uint4*)(bufp + OFF_AH + off)      = sa[0];
    *(uint4*)(bufp + OFF_AH + off + 16) = sa[1];
    *(uint4*)(bufp + OFF_AL + off)      = sa[2];
    *(uint4*)(bufp + OFF_AL + off + 16) = sa[3];
    *(uint4*)(bufp + OFF_BH + off)      = sb[0];
    *(uint4*)(bufp + OFF_BH + off + 16) = sb[1];
    *(uint4*)(bufp + OFF_BL + off)      = sb[2];
    *(uint4*)(bufp + OFF_BL + off + 16) = sb[3];
}

template<bool CONV2>
__global__ __launch_bounds__(256, 1) void conv_mma_kernel(
    const float* __restrict__ bias,
    const float* __restrict__ bias2,   // bs for conv2; ignored for conv1 (uses g_t)
    const int* __restrict__ neigh,
    float* __restrict__ outp)          // d_out for conv2; ignored for conv1 (uses g_h)
{
    extern __shared__ __align__(16) char smem[];
    const int NC = CONV2 ? 76 : 36;
    int tid = threadIdx.x;
    int lane = tid & 31, warp = tid >> 5;
    int wm = warp & 1, wn = warp >> 1;
    int rowStart = blockIdx.x * 128;
    int colB = blockIdx.y * 128;
    int b = rowStart >> 16;
    int v0 = rowStart & (VD - 1);
    size_t bbase = (size_t)b << 16;

    int* s_nidx = (int*)(smem + SM_NIDX);
    float* sg = (float*)(smem + SM_SG);
    float* sq = (float*)(smem + SM_SQ);
    for (int i = tid; i < 9 * 128; i += 256)
        s_nidx[i] = neigh[(v0 + (i & 127)) * 9 + (i >> 7)];
    if (!CONV2 && tid < 16) { sg[tid] = 0.f; sq[tid] = 0.f; }
    __syncthreads();   // s_nidx must be visible BEFORE the first gload reads it

    uint32_t sb32 = smem_to_u32(smem);
    int sel = lane >> 3, r8 = lane & 7;
    int a_off = (wm * 64 + ((sel & 1) << 3) + r8) * 80 + (((sel >> 1) & 1) << 4);
    int b_off = (wn * 32 + (((sel >> 1) & 1) << 3) + r8) * 80 + ((sel & 1) << 4);

    float acc[4][4][4];
    #pragma unroll
    for (int i = 0; i < 4; ++i)
        #pragma unroll
        for (int j = 0; j < 4; ++j)
            #pragma unroll
            for (int k = 0; k < 4; ++k) acc[i][j][k] = 0.f;

    uint4 sa[4], sb[4];
    gload<CONV2>(0, tid, rowStart, colB, bbase, s_nidx, sa, sb);
    sstore(smem + SM_BUF, tid, sa, sb);
    __syncthreads();

    for (int c = 0; c < NC; ++c) {
        int buf = c & 1;
        bool more = (c + 1 < NC);
        if (more) gload<CONV2>(c + 1, tid, rowStart, colB, bbase, s_nidx, sa, sb);

        uint32_t base = sb32 + SM_BUF + buf * BUFSZ;
        #pragma unroll
        for (int s = 0; s < 2; ++s) {
            int ka = s * 32;
            uint32_t ahf[4][4], bhf[4][2], blf[4][2];
            #pragma unroll
            for (int i = 0; i < 4; ++i)
                LDSM4(ahf[i][0], ahf[i][1], ahf[i][2], ahf[i][3],
                      base + OFF_AH + a_off + i * 1280 + ka);
            #pragma unroll
            for (int p = 0; p < 2; ++p) {
                uint32_t t0, t1, t2, t3;
                LDSM4(t0, t1, t2, t3, base + OFF_BH + b_off + p * 1280 + ka);
                bhf[2*p][0] = t0; bhf[2*p][1] = t1; bhf[2*p+1][0] = t2; bhf[2*p+1][1] = t3;
            }
            #pragma unroll
            for (int i = 0; i < 4; ++i)
                #pragma unroll
                for (int j = 0; j < 4; ++j) MMA_BF16(acc[i][j], ahf[i], bhf[j]);
            #pragma unroll
            for (int p = 0; p < 2; ++p) {
                uint32_t t0, t1, t2, t3;
                LDSM4(t0, t1, t2, t3, base + OFF_BL + b_off + p * 1280 + ka);
                blf[2*p][0] = t0; blf[2*p][1] = t1; blf[2*p+1][0] = t2; blf[2*p+1][1] = t3;
            }
            #pragma unroll
            for (int i = 0; i < 4; ++i)
                #pragma unroll
                for (int j = 0; j < 4; ++j) MMA_BF16(acc[i][j], ahf[i], blf[j]);
            #pragma unroll
            for (int i = 0; i < 4; ++i)
                LDSM4(ahf[i][0], ahf[i][1], ahf[i][2], ahf[i][3],
                      base + OFF_AL + a_off + i * 1280 + ka);
            #pragma unroll
            for (int i = 0; i < 4; ++i)
                #pragma unroll
                for (int j = 0; j < 4; ++j) MMA_BF16(acc[i][j], ahf[i], bhf[j]);
        }
        if (more) sstore(smem + SM_BUF + (buf ^ 1) * BUFSZ, tid, sa, sb);
        __syncthreads();
    }

    // ---- epilogue ----
    float* dst = CONV2 ? outp : g_h;
    int lr = lane >> 2;
    int lc = (lane & 3) * 2;
    #pragma unroll
    for (int j = 0; j < 4; ++j) {
        int col = colB + wn * 32 + j * 8 + lc;
        float ax = bias[col]     + (CONV2 ? bias2[col]     : g_t[b * COUTD + col]);
        float ay = bias[col + 1] + (CONV2 ? bias2[col + 1] : g_t[b * COUTD + col + 1]);
        float sj = 0.f, qj = 0.f;
        #pragma unroll
        for (int i = 0; i < 4; ++i) {
            int r0 = rowStart + wm * 64 + i * 16 + lr;
            float o0 = acc[i][j][0] + ax, o1 = acc[i][j][1] + ay;
            float o2 = acc[i][j][2] + ax, o3 = acc[i][j][3] + ay;
            float2 v0 = {o0, o1}, v1 = {o2, o3};
            *reinterpret_cast<float2*>(&dst[(size_t)r0 * COUTD + col]) = v0;
            *reinterpret_cast<float2*>(&dst[(size_t)(r0 + 8) * COUTD + col]) = v1;
            if (!CONV2) {
                sj += o0 + o1 + o2 + o3;
                qj += o0 * o0 + o1 * o1 + o2 * o2 + o3 * o3;
            }
        }
        if (!CONV2) {
            #pragma unroll
            for (int off = 16; off; off >>= 1) {
                sj += __shfl_xor_sync(0xFFFFFFFFu, sj, off);
                qj += __shfl_xor_sync(0xFFFFFFFFu, qj, off);
            }
            if (lane == 0) {
                atomicAdd(&sg[wn * 4 + j], sj);
                atomicAdd(&sq[wn * 4 + j], qj);
            }
        }
    }
    if (!CONV2) {
        __syncthreads();
        if (tid < 16) {
            int gidx = b * 32 + (colB >> 3) + tid;
            atomicAdd(&g_sum2[gidx], sg[tid]);
            atomicAdd(&g_sumsq2[gidx], sq[tid]);
        }
    }
}

// ================= launch =================
extern "C" void kernel_launch(void* const* d_in, const int* in_sizes, int n_in,
                              void* d_out, int out_size) {
    const float* x      = (const float*)d_in[0];
    const float* t_emb  = (const float*)d_in[1];
    const int*   neigh  = (const int*)d_in[2];
    const float* gn1_w  = (const float*)d_in[3];
    const float* gn1_b  = (const float*)d_in[4];
    const float* w1     = (const float*)d_in[5];
    const float* b1     = (const float*)d_in[6];
    const float* wt     = (const float*)d_in[7];
    const float* bt     = (const float*)d_in[8];
    const float* gn2_w  = (const float*)d_in[9];
    const float* gn2_b  = (const float*)d_in[10];
    const float* w2     = (const float*)d_in[11];
    const float* b2     = (const float*)d_in[12];
    const float* ws     = (const float*)d_in[13];
    const float* bs     = (const float*)d_in[14];
    float* out = (float*)d_out;

    static bool attr_set = false;
    if (!attr_set) {
        cudaFuncSetAttribute(conv_mma_kernel<false>, cudaFuncAttributeMaxDynamicSharedMemorySize, SMEMSZ);
        cudaFuncSetAttribute(conv_mma_kernel<true>,  cudaFuncAttributeMaxDynamicSharedMemorySize, SMEMSZ);
        attr_set = true;
    }

    zero_stats_kernel<<<1, 256>>>();
    gn1_stats_kernel<<<1024, 256>>>(x);
    finalize1_kernel<<<1, 64>>>();
    t_kernel<<<2, 256>>>(t_emb, wt, bt);
    prep_w_kernel<<<(294912 + 589824 + 32768 + 255) / 256, 256>>>(w1, w2, ws);
    hn1split_kernel<<<16384, 256>>>(x, gn1_w, gn1_b);
    conv_mma_kernel<false><<<dim3(1024, 2), 256, SMEMSZ>>>(b1, nullptr, neigh, nullptr);
    finalize2_kernel<<<1, 64>>>();
    hn2split_kernel<<<32768, 256>>>(gn2_w, gn2_b);
    conv_mma_kernel<true><<<dim3(1024, 2), 256, SMEMSZ>>>(b2, bs, neigh, out);
}